// round 6
// baseline (speedup 1.0000x reference)
#include <cuda_runtime.h>
#include <cuda_bf16.h>

// Problem constants
#define B_SZ   512
#define IN_F   512
#define OUT_F  64
#define KD     16
#define NF     (OUT_F * KD)   // 1024
#define KS     4              // k-splits in GEMM

typedef unsigned long long u64;

// Scratch: 4 partial M buffers + summed M, all [o][b][k]; S accum [j][o]
__device__ float g_Mp[KS][OUT_F * B_SZ * KD];
__device__ float g_M[OUT_F * B_SZ * KD];
__device__ float g_S[B_SZ * OUT_F];

// ---- packed f32x2 helpers (sm_103a) ---------------------------------------
__device__ __forceinline__ u64 fadd2(u64 a, u64 b) {
    u64 r; asm("add.rn.f32x2 %0, %1, %2;" : "=l"(r) : "l"(a), "l"(b)); return r;
}
__device__ __forceinline__ u64 ffma2(u64 a, u64 b, u64 c) {
    u64 r; asm("fma.rn.f32x2 %0, %1, %2, %3;" : "=l"(r) : "l"(a), "l"(b), "l"(c)); return r;
}
__device__ __forceinline__ u64 fabs2(u64 a) {
    return a & 0x7FFFFFFF7FFFFFFFULL;            // sign clear -> alu pipe
}
__device__ __forceinline__ u64 pack2(float lo, float hi) {
    u64 r; asm("mov.b64 %0, {%1, %2};" : "=l"(r) : "f"(lo), "f"(hi)); return r;
}
__device__ __forceinline__ void unpack2(u64 v, float& lo, float& hi) {
    asm("mov.b64 {%0, %1}, %2;" : "=f"(lo), "=f"(hi) : "l"(v));
}

// ---------------------------------------------------------------------------
// Kernel A: k-split GEMM.  Block (nt, mt, ks): 64x64 tile over K-chunk 128,
// partial -> g_Mp[ks][o][b][k].  256 threads, TK=16, 4x4 microtile, FFMA2.
// xsd padded to TK+1 so the per-kk A loads are bank-conflict-free.
// ---------------------------------------------------------------------------
#define TM 64
#define TN 64
#define TK 16
#define KC (IN_F / KS)        // 128

__global__ __launch_bounds__(256) void mbd_gemm_kernel(
    const float* __restrict__ x, const float* __restrict__ T)
{
    __shared__ float2 xsd[TM][TK + 1];  // duplicated A (a,a), PADDED row
    __shared__ float  Ts[TK][TN];

    const int tid = threadIdx.x;
    const int nt  = blockIdx.x;
    const int mt  = blockIdx.y;
    const int ks  = blockIdx.z;

    // g_S zeroing by the ks==0 plane (128 blocks x 256 = 32768)
    if (ks == 0) {
        int id = mt * 16 + nt;
        g_S[id * 256 + tid] = 0.0f;
    }

    const int tx = tid & 15;
    const int ty = tid >> 4;
    const int m0 = mt * TM;
    const int n0 = nt * TN;
    const int kb = ks * KC;
    const int r = ty * 4;
    const int c = tx * 4;

    u64 acc[4][2];
#pragma unroll
    for (int i = 0; i < 4; i++) { acc[i][0] = 0ULL; acc[i][1] = 0ULL; }

    for (int k0 = 0; k0 < KC; k0 += TK) {
        // A tile 64x16: one float4/thread, stored duplicated into padded rows
        {
            int idx = tid * 4;
            int m = idx >> 4;
            int k = idx & 15;
            float4 v = *(const float4*)&x[(m0 + m) * IN_F + kb + k0 + k];
            xsd[m][k + 0] = make_float2(v.x, v.x);
            xsd[m][k + 1] = make_float2(v.y, v.y);
            xsd[m][k + 2] = make_float2(v.z, v.z);
            xsd[m][k + 3] = make_float2(v.w, v.w);
        }
        // B tile 16x64: one float4/thread
        {
            int idx = tid * 4;
            int k = idx >> 6;
            int n = idx & 63;
            float4 v = *(const float4*)&T[(kb + k0 + k) * NF + n0 + n];
            *(float4*)&Ts[k][n] = v;
        }
        __syncthreads();

#pragma unroll
        for (int kk = 0; kk < TK; kk++) {
            u64 a0 = *(const u64*)&xsd[r + 0][kk];
            u64 a1 = *(const u64*)&xsd[r + 1][kk];
            u64 a2 = *(const u64*)&xsd[r + 2][kk];
            u64 a3 = *(const u64*)&xsd[r + 3][kk];
            ulonglong2 bb = *(const ulonglong2*)&Ts[kk][c];
            acc[0][0] = ffma2(a0, bb.x, acc[0][0]); acc[0][1] = ffma2(a0, bb.y, acc[0][1]);
            acc[1][0] = ffma2(a1, bb.x, acc[1][0]); acc[1][1] = ffma2(a1, bb.y, acc[1][1]);
            acc[2][0] = ffma2(a2, bb.x, acc[2][0]); acc[2][1] = ffma2(a2, bb.y, acc[2][1]);
            acc[3][0] = ffma2(a3, bb.x, acc[3][0]); acc[3][1] = ffma2(a3, bb.y, acc[3][1]);
        }
        __syncthreads();
    }

    const int of = n0 + c;
    const int o  = of >> 4;
    const int k  = of & 15;
    float* dst = g_Mp[ks];
#pragma unroll
    for (int ii = 0; ii < 4; ii++) {
        int b = m0 + r + ii;
        ulonglong2 v; v.x = acc[ii][0]; v.y = acc[ii][1];
        *(ulonglong2*)&dst[(o * B_SZ + b) * KD + k] = v;
    }
}

// ---------------------------------------------------------------------------
// Kernel R: g_M = sum of 4 k-split partials. 512 blocks x 256 thr, 1 float4 ea.
// ---------------------------------------------------------------------------
__global__ __launch_bounds__(256) void mbd_reduce_kernel(void)
{
    int e = blockIdx.x * 256 + threadIdx.x;    // float4 index, 131072 total
    float4 a = ((const float4*)g_Mp[0])[e];
    float4 b = ((const float4*)g_Mp[1])[e];
    float4 c = ((const float4*)g_Mp[2])[e];
    float4 d = ((const float4*)g_Mp[3])[e];
    ((float4*)g_M)[e] = make_float4((a.x + b.x) + (c.x + d.x),
                                    (a.y + b.y) + (c.y + d.y),
                                    (a.z + b.z) + (c.z + d.z),
                                    (a.w + b.w) + (c.w + d.w));
}

// ---------------------------------------------------------------------------
// Kernel B: pairwise tiles. grid (64 o, 4 j-chunk(128), 8 i-chunk(64)),
// 128 threads; thread = one j, 64 i's. Partial S -> REDG into g_S[j][o].
// ---------------------------------------------------------------------------
__global__ __launch_bounds__(128) void mbd_pairwise_kernel(void)
{
    __shared__ float sJ[128 * KD];             // 8 KB
    __shared__ float sI[64 * KD];              // 4 KB

    const int o   = blockIdx.x;
    const int jc  = blockIdx.y;                // j-chunk (128 j's)
    const int q   = blockIdx.z;                // i-chunk (64 i's)
    const int tid = threadIdx.x;
    const int j   = jc * 128 + tid;

    {
        const float4* bJ = (const float4*)(g_M + (o * B_SZ + jc * 128) * KD);
        const float4* bI = (const float4*)(g_M + (o * B_SZ + q * 64) * KD);
        float4* dJ = (float4*)sJ;
        float4* dI = (float4*)sI;
#pragma unroll
        for (int t = 0; t < 4; t++) dJ[tid + t * 128] = bJ[tid + t * 128];
#pragma unroll
        for (int t = 0; t < 2; t++) dI[tid + t * 128] = bI[tid + t * 128];
    }
    __syncthreads();

    // Pre-negated packed row j
    u64 mjn[8];
#pragma unroll
    for (int p = 0; p < 8; p++)
        mjn[p] = pack2(-sJ[tid * KD + 2 * p], -sJ[tid * KD + 2 * p + 1]);

    const ulonglong2* s2 = (const ulonglong2*)sI;
    float S = 0.f;

#pragma unroll 2
    for (int i = 0; i < 64; i++) {
        ulonglong2 v0 = s2[i * 4 + 0];         // warp-uniform -> LDS broadcast
        ulonglong2 v1 = s2[i * 4 + 1];
        ulonglong2 v2 = s2[i * 4 + 2];
        ulonglong2 v3 = s2[i * 4 + 3];
        u64 a0 = fabs2(fadd2(v0.x, mjn[0]));
        u64 a1 = fabs2(fadd2(v0.y, mjn[1]));
        u64 a2 = fabs2(fadd2(v1.x, mjn[2]));
        u64 a3 = fabs2(fadd2(v1.y, mjn[3]));
        u64 a4 = fabs2(fadd2(v2.x, mjn[4]));
        u64 a5 = fabs2(fadd2(v2.y, mjn[5]));
        u64 a6 = fabs2(fadd2(v3.x, mjn[6]));
        u64 a7 = fabs2(fadd2(v3.y, mjn[7]));
        u64 t = fadd2(fadd2(fadd2(a0, a1), fadd2(a2, a3)),
                      fadd2(fadd2(a4, a5), fadd2(a6, a7)));
        float lo, hi; unpack2(t, lo, hi);
        S += __expf(-(lo + hi));
    }

    atomicAdd(&g_S[j * OUT_F + o], S);         // REDG
}

// ---------------------------------------------------------------------------
// Kernel C: out[j,o] = w[j] * (g_S[j,o] - 1)
// ---------------------------------------------------------------------------
__global__ __launch_bounds__(256) void mbd_finalize_kernel(
    const float* __restrict__ w, float* __restrict__ out)
{
    int idx = blockIdx.x * 256 + threadIdx.x;  // 0 .. 32767
    int j = idx >> 6;
    out[idx] = w[j] * (g_S[idx] - 1.0f);
}

// ---------------------------------------------------------------------------
extern "C" void kernel_launch(void* const* d_in, const int* in_sizes, int n_in,
                              void* d_out, int out_size)
{
    const float* x = (const float*)d_in[0];   // [512, 512]
    const float* w = (const float*)d_in[1];   // [1, 512]
    const float* T = (const float*)d_in[2];   // [512, 64, 16]
    float* out = (float*)d_out;               // [512, 64]

    (void)in_sizes; (void)n_in; (void)out_size;

    mbd_gemm_kernel<<<dim3(NF / TN, B_SZ / TM, KS), 256>>>(x, T);
    mbd_reduce_kernel<<<512, 256>>>();
    mbd_pairwise_kernel<<<dim3(OUT_F, 4, 8), 128>>>();
    mbd_finalize_kernel<<<(B_SZ * OUT_F) / 256, 256>>>(w, out);
}

// round 7
// speedup vs baseline: 1.5346x; 1.5346x over previous
#include <cuda_runtime.h>
#include <cuda_bf16.h>

// Problem constants
#define B_SZ   512
#define IN_F   512
#define OUT_F  64
#define KD     16
#define NF     (OUT_F * KD)   // 1024
#define KS     4              // k-splits in GEMM

typedef unsigned long long u64;

// Scratch: 4 partial M buffers laid out [o][b][k] (4 x 2 MB),
// S accumulator laid out [j][o] (128 KB)
__device__ float g_Mp[KS][OUT_F * B_SZ * KD];
__device__ float g_S[B_SZ * OUT_F];

// ---- packed f32x2 helpers (sm_103a) ---------------------------------------
__device__ __forceinline__ u64 fadd2(u64 a, u64 b) {
    u64 r; asm("add.rn.f32x2 %0, %1, %2;" : "=l"(r) : "l"(a), "l"(b)); return r;
}
__device__ __forceinline__ u64 ffma2(u64 a, u64 b, u64 c) {
    u64 r; asm("fma.rn.f32x2 %0, %1, %2, %3;" : "=l"(r) : "l"(a), "l"(b), "l"(c)); return r;
}
__device__ __forceinline__ u64 fabs2(u64 a) {
    return a & 0x7FFFFFFF7FFFFFFFULL;            // sign clear -> alu pipe
}
__device__ __forceinline__ u64 pack2(float lo, float hi) {
    u64 r; asm("mov.b64 %0, {%1, %2};" : "=l"(r) : "f"(lo), "f"(hi)); return r;
}
__device__ __forceinline__ void unpack2(u64 v, float& lo, float& hi) {
    asm("mov.b64 {%0, %1}, %2;" : "=f"(lo), "=f"(hi) : "l"(v));
}

// ---------------------------------------------------------------------------
// Kernel A: k-split GEMM.  Block (nt, mt, ks): 64x64 tile over K-chunk 128,
// partial -> g_Mp[ks][o][b][k].  256 threads, TK=16, 4x4 microtile, FFMA2.
// ONLY change vs R5: xsd rows padded (+1 float2) -> conflict-free LDS/STS.
// ---------------------------------------------------------------------------
#define TM 64
#define TN 64
#define TK 16
#define KC (IN_F / KS)        // 128

__global__ __launch_bounds__(256) void mbd_gemm_kernel(
    const float* __restrict__ x, const float* __restrict__ T)
{
    __shared__ float2 xsd[TM][TK + 1];  // duplicated A (a,a), PADDED rows
    __shared__ float  Ts[TK][TN];

    const int tid = threadIdx.x;
    const int nt  = blockIdx.x;
    const int mt  = blockIdx.y;
    const int ks  = blockIdx.z;

    // g_S zeroing by the ks==0 plane (128 blocks x 256 = 32768)
    if (ks == 0) {
        int id = mt * 16 + nt;
        g_S[id * 256 + tid] = 0.0f;
    }

    const int tx = tid & 15;
    const int ty = tid >> 4;
    const int m0 = mt * TM;
    const int n0 = nt * TN;
    const int kb = ks * KC;
    const int r = ty * 4;
    const int c = tx * 4;

    u64 acc[4][2];
#pragma unroll
    for (int i = 0; i < 4; i++) { acc[i][0] = 0ULL; acc[i][1] = 0ULL; }

    for (int k0 = 0; k0 < KC; k0 += TK) {
        // A tile 64x16 = 1024 floats: one float4/thread, stored duplicated
        {
            int idx = tid * 4;
            int m = idx >> 4;
            int k = idx & 15;
            float4 v = *(const float4*)&x[(m0 + m) * IN_F + kb + k0 + k];
            xsd[m][k + 0] = make_float2(v.x, v.x);
            xsd[m][k + 1] = make_float2(v.y, v.y);
            xsd[m][k + 2] = make_float2(v.z, v.z);
            xsd[m][k + 3] = make_float2(v.w, v.w);
        }
        // B tile 16x64 = 1024 floats: one float4/thread
        {
            int idx = tid * 4;
            int k = idx >> 6;
            int n = idx & 63;
            float4 v = *(const float4*)&T[(kb + k0 + k) * NF + n0 + n];
            *(float4*)&Ts[k][n] = v;
        }
        __syncthreads();

#pragma unroll
        for (int kk = 0; kk < TK; kk++) {
            u64 a0 = *(const u64*)&xsd[r + 0][kk];
            u64 a1 = *(const u64*)&xsd[r + 1][kk];
            u64 a2 = *(const u64*)&xsd[r + 2][kk];
            u64 a3 = *(const u64*)&xsd[r + 3][kk];
            ulonglong2 bb = *(const ulonglong2*)&Ts[kk][c];
            acc[0][0] = ffma2(a0, bb.x, acc[0][0]); acc[0][1] = ffma2(a0, bb.y, acc[0][1]);
            acc[1][0] = ffma2(a1, bb.x, acc[1][0]); acc[1][1] = ffma2(a1, bb.y, acc[1][1]);
            acc[2][0] = ffma2(a2, bb.x, acc[2][0]); acc[2][1] = ffma2(a2, bb.y, acc[2][1]);
            acc[3][0] = ffma2(a3, bb.x, acc[3][0]); acc[3][1] = ffma2(a3, bb.y, acc[3][1]);
        }
        __syncthreads();
    }

    // Epilogue: partial -> g_Mp[ks][o][b][k]. c multiple of 4 -> one o.
    const int of = n0 + c;
    const int o  = of >> 4;
    const int k  = of & 15;
    float* dst = g_Mp[ks];
#pragma unroll
    for (int ii = 0; ii < 4; ii++) {
        int b = m0 + r + ii;
        ulonglong2 v; v.x = acc[ii][0]; v.y = acc[ii][1];
        *(ulonglong2*)&dst[(o * B_SZ + b) * KD + k] = v;
    }
}

// ---------------------------------------------------------------------------
// Kernel B: fine-grained pairwise tiles (UNCHANGED from R5 — proven 27us).
// grid (64 o, 4 j-chunk, 4 i-quarter), 128 threads; thread = one j, 128 i's.
// Staging sums the 4 GEMM partials. Partial S -> REDG into g_S[j][o].
// ---------------------------------------------------------------------------
__global__ __launch_bounds__(128) void mbd_pairwise_kernel(void)
{
    __shared__ float sJ[128 * KD];             // 8 KB
    __shared__ float sI[128 * KD];             // 8 KB

    const int o   = blockIdx.x;
    const int jc  = blockIdx.y;                // j-chunk (128 j's)
    const int q   = blockIdx.z;                // i-quarter (128 i's)
    const int tid = threadIdx.x;
    const int j   = jc * 128 + tid;

    // Stage j-rows and i-rows, summing the 4 k-split partials
    {
        const int offJ = (o * B_SZ + jc * 128) * KD / 4;   // float4 units
        const int offI = (o * B_SZ + q  * 128) * KD / 4;
        float4* dJ = (float4*)sJ;
        float4* dI = (float4*)sI;
#pragma unroll
        for (int t = 0; t < 4; t++) {
            int e = tid + t * 128;
            float4 aJ = ((const float4*)g_Mp[0])[offJ + e];
            float4 bJ = ((const float4*)g_Mp[1])[offJ + e];
            float4 cJ = ((const float4*)g_Mp[2])[offJ + e];
            float4 eJ = ((const float4*)g_Mp[3])[offJ + e];
            dJ[e] = make_float4((aJ.x + bJ.x) + (cJ.x + eJ.x),
                                (aJ.y + bJ.y) + (cJ.y + eJ.y),
                                (aJ.z + bJ.z) + (cJ.z + eJ.z),
                                (aJ.w + bJ.w) + (cJ.w + eJ.w));
            float4 aI = ((const float4*)g_Mp[0])[offI + e];
            float4 bI = ((const float4*)g_Mp[1])[offI + e];
            float4 cI = ((const float4*)g_Mp[2])[offI + e];
            float4 eI = ((const float4*)g_Mp[3])[offI + e];
            dI[e] = make_float4((aI.x + bI.x) + (cI.x + eI.x),
                                (aI.y + bI.y) + (cI.y + eI.y),
                                (aI.z + bI.z) + (cI.z + eI.z),
                                (aI.w + bI.w) + (cI.w + eI.w));
        }
    }
    __syncthreads();

    // Pre-negated packed row j
    u64 mjn[8];
#pragma unroll
    for (int p = 0; p < 8; p++)
        mjn[p] = pack2(-sJ[tid * KD + 2 * p], -sJ[tid * KD + 2 * p + 1]);

    const ulonglong2* s2 = (const ulonglong2*)sI;
    float S = 0.f;

#pragma unroll 2
    for (int i = 0; i < 128; i++) {
        ulonglong2 v0 = s2[i * 4 + 0];         // warp-uniform -> LDS broadcast
        ulonglong2 v1 = s2[i * 4 + 1];
        ulonglong2 v2 = s2[i * 4 + 2];
        ulonglong2 v3 = s2[i * 4 + 3];
        u64 a0 = fabs2(fadd2(v0.x, mjn[0]));
        u64 a1 = fabs2(fadd2(v0.y, mjn[1]));
        u64 a2 = fabs2(fadd2(v1.x, mjn[2]));
        u64 a3 = fabs2(fadd2(v1.y, mjn[3]));
        u64 a4 = fabs2(fadd2(v2.x, mjn[4]));
        u64 a5 = fabs2(fadd2(v2.y, mjn[5]));
        u64 a6 = fabs2(fadd2(v3.x, mjn[6]));
        u64 a7 = fabs2(fadd2(v3.y, mjn[7]));
        u64 t = fadd2(fadd2(fadd2(a0, a1), fadd2(a2, a3)),
                      fadd2(fadd2(a4, a5), fadd2(a6, a7)));
        float lo, hi; unpack2(t, lo, hi);
        S += __expf(-(lo + hi));
    }

    atomicAdd(&g_S[j * OUT_F + o], S);         // REDG, 131K total adds
}

// ---------------------------------------------------------------------------
// Kernel C: out[j,o] = w[j] * (g_S[j,o] - 1)   (coalesced both sides)
// ---------------------------------------------------------------------------
__global__ __launch_bounds__(256) void mbd_finalize_kernel(
    const float* __restrict__ w, float* __restrict__ out)
{
    int idx = blockIdx.x * 256 + threadIdx.x;  // 0 .. 32767
    int j = idx >> 6;
    out[idx] = w[j] * (g_S[idx] - 1.0f);
}

// ---------------------------------------------------------------------------
extern "C" void kernel_launch(void* const* d_in, const int* in_sizes, int n_in,
                              void* d_out, int out_size)
{
    const float* x = (const float*)d_in[0];   // [512, 512]
    const float* w = (const float*)d_in[1];   // [1, 512]
    const float* T = (const float*)d_in[2];   // [512, 64, 16]
    float* out = (float*)d_out;               // [512, 64]

    (void)in_sizes; (void)n_in; (void)out_size;

    mbd_gemm_kernel<<<dim3(NF / TN, B_SZ / TM, KS), 256>>>(x, T);
    mbd_pairwise_kernel<<<dim3(OUT_F, 4, 4), 128>>>();
    mbd_finalize_kernel<<<(B_SZ * OUT_F) / 256, 256>>>(w, out);
}

// round 8
// speedup vs baseline: 1.5855x; 1.0331x over previous
#include <cuda_runtime.h>
#include <cuda_bf16.h>

// Problem constants
#define B_SZ   512
#define IN_F   512
#define OUT_F  64
#define KD     16
#define NF     (OUT_F * KD)   // 1024
#define KS     4              // k-splits in GEMM

typedef unsigned long long u64;

// Scratch: 4 partial M buffers [o][b][k]; S accumulator [o][j]; group counters
__device__ float g_Mp[KS][OUT_F * B_SZ * KD];
__device__ float g_S[OUT_F * B_SZ];
__device__ unsigned int g_cnt[OUT_F * 4];      // zero-init, self-resetting

// ---- packed f32x2 helpers (sm_103a) ---------------------------------------
__device__ __forceinline__ u64 fadd2(u64 a, u64 b) {
    u64 r; asm("add.rn.f32x2 %0, %1, %2;" : "=l"(r) : "l"(a), "l"(b)); return r;
}
__device__ __forceinline__ u64 ffma2(u64 a, u64 b, u64 c) {
    u64 r; asm("fma.rn.f32x2 %0, %1, %2, %3;" : "=l"(r) : "l"(a), "l"(b), "l"(c)); return r;
}
__device__ __forceinline__ u64 fabs2(u64 a) {
    return a & 0x7FFFFFFF7FFFFFFFULL;            // sign clear -> alu pipe
}
__device__ __forceinline__ u64 pack2(float lo, float hi) {
    u64 r; asm("mov.b64 %0, {%1, %2};" : "=l"(r) : "f"(lo), "f"(hi)); return r;
}
__device__ __forceinline__ void unpack2(u64 v, float& lo, float& hi) {
    asm("mov.b64 {%0, %1}, %2;" : "=f"(lo), "=f"(hi) : "l"(v));
}

// ---------------------------------------------------------------------------
// Kernel A: k-split GEMM, double-buffered.
// Block (nt, mt, ks): 64x64 tile over K-chunk 128 -> g_Mp[ks][o][b][k].
// 256 threads, TK=16, 4x4 microtile, FFMA2, duplicated-A smem.
// ---------------------------------------------------------------------------
#define TM 64
#define TN 64
#define TK 16
#define KC (IN_F / KS)        // 128
#define NSTEP (KC / TK)       // 8

__global__ __launch_bounds__(256) void mbd_gemm_kernel(
    const float* __restrict__ x, const float* __restrict__ T)
{
    __shared__ float2 xsd[2][TM][TK + 1];   // duplicated A (a,a)
    __shared__ float  Ts[2][TK][TN];

    const int tid = threadIdx.x;
    const int nt  = blockIdx.x;
    const int mt  = blockIdx.y;
    const int ks  = blockIdx.z;

    // g_S zeroing by the ks==0 plane (128 blocks x 256 = 32768)
    if (ks == 0) {
        int id = mt * 16 + nt;
        g_S[id * 256 + tid] = 0.0f;
    }

    const int tx = tid & 15;
    const int ty = tid >> 4;
    const int m0 = mt * TM;
    const int n0 = nt * TN;
    const int kb = ks * KC;
    const int r = ty * 4;
    const int c = tx * 4;

    // Loader coordinates (fixed per thread)
    const int lm = (tid * 4) >> 4, lk = (tid * 4) & 15;   // A: 64x16
    const int bk = (tid * 4) >> 6, bn = (tid * 4) & 63;   // B: 16x64
    const float* xp = &x[(m0 + lm) * IN_F + kb + lk];
    const float* Tp = &T[(kb + bk) * NF + n0 + bn];

    u64 acc[4][2];
#pragma unroll
    for (int i = 0; i < 4; i++) { acc[i][0] = 0ULL; acc[i][1] = 0ULL; }

    // Prologue: stage step 0 into buffer 0
    {
        float4 va = *(const float4*)xp;
        float4 vb = *(const float4*)Tp;
        xsd[0][lm][lk + 0] = make_float2(va.x, va.x);
        xsd[0][lm][lk + 1] = make_float2(va.y, va.y);
        xsd[0][lm][lk + 2] = make_float2(va.z, va.z);
        xsd[0][lm][lk + 3] = make_float2(va.w, va.w);
        *(float4*)&Ts[0][bk][bn] = vb;
    }

    int buf = 0;
#pragma unroll
    for (int s = 0; s < NSTEP; s++) {
        __syncthreads();

        // Prefetch next step's tiles into registers (overlaps with compute)
        float4 na, nb;
        if (s < NSTEP - 1) {
            na = *(const float4*)(xp + (s + 1) * TK);
            nb = *(const float4*)(Tp + (s + 1) * TK * NF);
        }

#pragma unroll
        for (int kk = 0; kk < TK; kk++) {
            u64 a0 = *(const u64*)&xsd[buf][r + 0][kk];
            u64 a1 = *(const u64*)&xsd[buf][r + 1][kk];
            u64 a2 = *(const u64*)&xsd[buf][r + 2][kk];
            u64 a3 = *(const u64*)&xsd[buf][r + 3][kk];
            ulonglong2 bb = *(const ulonglong2*)&Ts[buf][kk][c];
            acc[0][0] = ffma2(a0, bb.x, acc[0][0]); acc[0][1] = ffma2(a0, bb.y, acc[0][1]);
            acc[1][0] = ffma2(a1, bb.x, acc[1][0]); acc[1][1] = ffma2(a1, bb.y, acc[1][1]);
            acc[2][0] = ffma2(a2, bb.x, acc[2][0]); acc[2][1] = ffma2(a2, bb.y, acc[2][1]);
            acc[3][0] = ffma2(a3, bb.x, acc[3][0]); acc[3][1] = ffma2(a3, bb.y, acc[3][1]);
        }

        // Store prefetched tiles into the other buffer (safe: that buffer's
        // readers all passed the syncthreads at the top of this step)
        if (s < NSTEP - 1) {
            int nb2 = buf ^ 1;
            xsd[nb2][lm][lk + 0] = make_float2(na.x, na.x);
            xsd[nb2][lm][lk + 1] = make_float2(na.y, na.y);
            xsd[nb2][lm][lk + 2] = make_float2(na.z, na.z);
            xsd[nb2][lm][lk + 3] = make_float2(na.w, na.w);
            *(float4*)&Ts[nb2][bk][bn] = nb;
        }
        buf ^= 1;
    }

    // Epilogue: partial -> g_Mp[ks][o][b][k]. c multiple of 4 -> one o.
    const int of = n0 + c;
    const int o  = of >> 4;
    const int k  = of & 15;
    float* dst = g_Mp[ks];
#pragma unroll
    for (int ii = 0; ii < 4; ii++) {
        int b = m0 + r + ii;
        ulonglong2 v; v.x = acc[ii][0]; v.y = acc[ii][1];
        *(ulonglong2*)&dst[(o * B_SZ + b) * KD + k] = v;
    }
}

// ---------------------------------------------------------------------------
// Kernel B: pairwise tiles + fused finalize.
// grid (64 o, 4 j-chunk, 4 i-quarter), 128 threads; thread = one j, 128 i's.
// Staging sums 4 GEMM partials. REDG into g_S[o][j]; last block of each
// (o,jc) group applies  out[j,o] = w[j] * (g_S[o][j] - 1).
// ---------------------------------------------------------------------------
__global__ __launch_bounds__(128) void mbd_pairwise_kernel(
    const float* __restrict__ w, float* __restrict__ out)
{
    __shared__ float sJ[128 * KD];             // 8 KB
    __shared__ float sI[128 * KD];             // 8 KB
    __shared__ int last;

    const int o   = blockIdx.x;
    const int jc  = blockIdx.y;                // j-chunk (128 j's)
    const int q   = blockIdx.z;                // i-quarter (128 i's)
    const int tid = threadIdx.x;
    const int j   = jc * 128 + tid;

    // Stage j-rows and i-rows, summing the 4 k-split partials
    {
        const int offJ = (o * B_SZ + jc * 128) * KD / 4;   // float4 units
        const int offI = (o * B_SZ + q  * 128) * KD / 4;
        float4* dJ = (float4*)sJ;
        float4* dI = (float4*)sI;
#pragma unroll
        for (int t = 0; t < 4; t++) {
            int e = tid + t * 128;
            float4 aJ = ((const float4*)g_Mp[0])[offJ + e];
            float4 bJ = ((const float4*)g_Mp[1])[offJ + e];
            float4 cJ = ((const float4*)g_Mp[2])[offJ + e];
            float4 eJ = ((const float4*)g_Mp[3])[offJ + e];
            dJ[e] = make_float4((aJ.x + bJ.x) + (cJ.x + eJ.x),
                                (aJ.y + bJ.y) + (cJ.y + eJ.y),
                                (aJ.z + bJ.z) + (cJ.z + eJ.z),
                                (aJ.w + bJ.w) + (cJ.w + eJ.w));
            float4 aI = ((const float4*)g_Mp[0])[offI + e];
            float4 bI = ((const float4*)g_Mp[1])[offI + e];
            float4 cI = ((const float4*)g_Mp[2])[offI + e];
            float4 eI = ((const float4*)g_Mp[3])[offI + e];
            dI[e] = make_float4((aI.x + bI.x) + (cI.x + eI.x),
                                (aI.y + bI.y) + (cI.y + eI.y),
                                (aI.z + bI.z) + (cI.z + eI.z),
                                (aI.w + bI.w) + (cI.w + eI.w));
        }
    }
    __syncthreads();

    // Pre-negated packed row j
    u64 mjn[8];
#pragma unroll
    for (int p = 0; p < 8; p++)
        mjn[p] = pack2(-sJ[tid * KD + 2 * p], -sJ[tid * KD + 2 * p + 1]);

    const ulonglong2* s2 = (const ulonglong2*)sI;
    float S = 0.f;

#pragma unroll 2
    for (int i = 0; i < 128; i++) {
        ulonglong2 v0 = s2[i * 4 + 0];         // warp-uniform -> LDS broadcast
        ulonglong2 v1 = s2[i * 4 + 1];
        ulonglong2 v2 = s2[i * 4 + 2];
        ulonglong2 v3 = s2[i * 4 + 3];
        u64 a0 = fabs2(fadd2(v0.x, mjn[0]));
        u64 a1 = fabs2(fadd2(v0.y, mjn[1]));
        u64 a2 = fabs2(fadd2(v1.x, mjn[2]));
        u64 a3 = fabs2(fadd2(v1.y, mjn[3]));
        u64 a4 = fabs2(fadd2(v2.x, mjn[4]));
        u64 a5 = fabs2(fadd2(v2.y, mjn[5]));
        u64 a6 = fabs2(fadd2(v3.x, mjn[6]));
        u64 a7 = fabs2(fadd2(v3.y, mjn[7]));
        u64 t = fadd2(fadd2(fadd2(a0, a1), fadd2(a2, a3)),
                      fadd2(fadd2(a4, a5), fadd2(a6, a7)));
        float lo, hi; unpack2(t, lo, hi);
        S += __expf(-(lo + hi));
    }

    atomicAdd(&g_S[o * B_SZ + j], S);          // coalesced REDG

    // Last block of the (o, jc) group applies the finalize
    __threadfence();
    __syncthreads();
    if (tid == 0)
        last = (atomicAdd(&g_cnt[o * 4 + jc], 1u) == 3u);
    __syncthreads();
    if (last) {
        __threadfence();                       // acquire: see peers' REDG
        float s = g_S[o * B_SZ + j];           // coalesced
        out[j * OUT_F + o] = w[j] * (s - 1.0f);
        if (tid == 0) g_cnt[o * 4 + jc] = 0u;  // reset for next graph replay
    }
}

// ---------------------------------------------------------------------------
extern "C" void kernel_launch(void* const* d_in, const int* in_sizes, int n_in,
                              void* d_out, int out_size)
{
    const float* x = (const float*)d_in[0];   // [512, 512]
    const float* w = (const float*)d_in[1];   // [1, 512]
    const float* T = (const float*)d_in[2];   // [512, 64, 16]
    float* out = (float*)d_out;               // [512, 64]

    (void)in_sizes; (void)n_in; (void)out_size;

    mbd_gemm_kernel<<<dim3(NF / TN, B_SZ / TM, KS), 256>>>(x, T);
    mbd_pairwise_kernel<<<dim3(OUT_F, 4, 4), 128>>>(w, out);
}

// round 9
// speedup vs baseline: 1.6416x; 1.0354x over previous
#include <cuda_runtime.h>
#include <cuda_bf16.h>

// Problem constants
#define B_SZ   512
#define IN_F   512
#define OUT_F  64
#define KD     16
#define NF     (OUT_F * KD)   // 1024
#define KS     4              // k-splits in GEMM

typedef unsigned long long u64;

// Scratch: 4 partial M buffers [o][b][k]; S accumulator [o][j]; group counters
__device__ float g_Mp[KS][OUT_F * B_SZ * KD];
__device__ float g_S[OUT_F * B_SZ];
__device__ unsigned int g_cnt[OUT_F * 4];      // zero-init, self-resetting

// ---- packed f32x2 helpers (sm_103a) ---------------------------------------
__device__ __forceinline__ u64 fadd2(u64 a, u64 b) {
    u64 r; asm("add.rn.f32x2 %0, %1, %2;" : "=l"(r) : "l"(a), "l"(b)); return r;
}
__device__ __forceinline__ u64 ffma2(u64 a, u64 b, u64 c) {
    u64 r; asm("fma.rn.f32x2 %0, %1, %2, %3;" : "=l"(r) : "l"(a), "l"(b), "l"(c)); return r;
}
__device__ __forceinline__ u64 fabs2(u64 a) {
    return a & 0x7FFFFFFF7FFFFFFFULL;            // sign clear -> alu pipe
}
__device__ __forceinline__ u64 pack2(float lo, float hi) {
    u64 r; asm("mov.b64 %0, {%1, %2};" : "=l"(r) : "f"(lo), "f"(hi)); return r;
}
__device__ __forceinline__ void unpack2(u64 v, float& lo, float& hi) {
    asm("mov.b64 {%0, %1}, %2;" : "=f"(lo), "=f"(hi) : "l"(v));
}

// ---------------------------------------------------------------------------
// Kernel A: k-split GEMM, double-buffered (UNCHANGED from R8).
// ---------------------------------------------------------------------------
#define TM 64
#define TN 64
#define TK 16
#define KC (IN_F / KS)        // 128
#define NSTEP (KC / TK)       // 8

__global__ __launch_bounds__(256) void mbd_gemm_kernel(
    const float* __restrict__ x, const float* __restrict__ T)
{
    __shared__ float2 xsd[2][TM][TK + 1];   // duplicated A (a,a)
    __shared__ float  Ts[2][TK][TN];

    const int tid = threadIdx.x;
    const int nt  = blockIdx.x;
    const int mt  = blockIdx.y;
    const int ks  = blockIdx.z;

    if (ks == 0) {
        int id = mt * 16 + nt;
        g_S[id * 256 + tid] = 0.0f;
    }

    const int tx = tid & 15;
    const int ty = tid >> 4;
    const int m0 = mt * TM;
    const int n0 = nt * TN;
    const int kb = ks * KC;
    const int r = ty * 4;
    const int c = tx * 4;

    const int lm = (tid * 4) >> 4, lk = (tid * 4) & 15;
    const int bk = (tid * 4) >> 6, bn = (tid * 4) & 63;
    const float* xp = &x[(m0 + lm) * IN_F + kb + lk];
    const float* Tp = &T[(kb + bk) * NF + n0 + bn];

    u64 acc[4][2];
#pragma unroll
    for (int i = 0; i < 4; i++) { acc[i][0] = 0ULL; acc[i][1] = 0ULL; }

    {
        float4 va = *(const float4*)xp;
        float4 vb = *(const float4*)Tp;
        xsd[0][lm][lk + 0] = make_float2(va.x, va.x);
        xsd[0][lm][lk + 1] = make_float2(va.y, va.y);
        xsd[0][lm][lk + 2] = make_float2(va.z, va.z);
        xsd[0][lm][lk + 3] = make_float2(va.w, va.w);
        *(float4*)&Ts[0][bk][bn] = vb;
    }

    int buf = 0;
#pragma unroll
    for (int s = 0; s < NSTEP; s++) {
        __syncthreads();

        float4 na, nb;
        if (s < NSTEP - 1) {
            na = *(const float4*)(xp + (s + 1) * TK);
            nb = *(const float4*)(Tp + (s + 1) * TK * NF);
        }

#pragma unroll
        for (int kk = 0; kk < TK; kk++) {
            u64 a0 = *(const u64*)&xsd[buf][r + 0][kk];
            u64 a1 = *(const u64*)&xsd[buf][r + 1][kk];
            u64 a2 = *(const u64*)&xsd[buf][r + 2][kk];
            u64 a3 = *(const u64*)&xsd[buf][r + 3][kk];
            ulonglong2 bb = *(const ulonglong2*)&Ts[buf][kk][c];
            acc[0][0] = ffma2(a0, bb.x, acc[0][0]); acc[0][1] = ffma2(a0, bb.y, acc[0][1]);
            acc[1][0] = ffma2(a1, bb.x, acc[1][0]); acc[1][1] = ffma2(a1, bb.y, acc[1][1]);
            acc[2][0] = ffma2(a2, bb.x, acc[2][0]); acc[2][1] = ffma2(a2, bb.y, acc[2][1]);
            acc[3][0] = ffma2(a3, bb.x, acc[3][0]); acc[3][1] = ffma2(a3, bb.y, acc[3][1]);
        }

        if (s < NSTEP - 1) {
            int nb2 = buf ^ 1;
            xsd[nb2][lm][lk + 0] = make_float2(na.x, na.x);
            xsd[nb2][lm][lk + 1] = make_float2(na.y, na.y);
            xsd[nb2][lm][lk + 2] = make_float2(na.z, na.z);
            xsd[nb2][lm][lk + 3] = make_float2(na.w, na.w);
            *(float4*)&Ts[nb2][bk][bn] = nb;
        }
        buf ^= 1;
    }

    const int of = n0 + c;
    const int o  = of >> 4;
    const int k  = of & 15;
    float* dst = g_Mp[ks];
#pragma unroll
    for (int ii = 0; ii < 4; ii++) {
        int b = m0 + r + ii;
        ulonglong2 v; v.x = acc[ii][0]; v.y = acc[ii][1];
        *(ulonglong2*)&dst[(o * B_SZ + b) * KD + k] = v;
    }
}

// ---------------------------------------------------------------------------
// Kernel B: pairwise tiles + fused finalize.
// CHANGE vs R8: i-loop unrolled x4 with 4 independent accumulators (ILP).
// ---------------------------------------------------------------------------
__device__ __forceinline__ float pair_term(const ulonglong2* __restrict__ s2,
                                           const u64* __restrict__ mjn, int i)
{
    ulonglong2 v0 = s2[i * 4 + 0];
    ulonglong2 v1 = s2[i * 4 + 1];
    ulonglong2 v2 = s2[i * 4 + 2];
    ulonglong2 v3 = s2[i * 4 + 3];
    u64 a0 = fabs2(fadd2(v0.x, mjn[0]));
    u64 a1 = fabs2(fadd2(v0.y, mjn[1]));
    u64 a2 = fabs2(fadd2(v1.x, mjn[2]));
    u64 a3 = fabs2(fadd2(v1.y, mjn[3]));
    u64 a4 = fabs2(fadd2(v2.x, mjn[4]));
    u64 a5 = fabs2(fadd2(v2.y, mjn[5]));
    u64 a6 = fabs2(fadd2(v3.x, mjn[6]));
    u64 a7 = fabs2(fadd2(v3.y, mjn[7]));
    u64 t = fadd2(fadd2(fadd2(a0, a1), fadd2(a2, a3)),
                  fadd2(fadd2(a4, a5), fadd2(a6, a7)));
    float lo, hi; unpack2(t, lo, hi);
    return __expf(-(lo + hi));
}

__global__ __launch_bounds__(128) void mbd_pairwise_kernel(
    const float* __restrict__ w, float* __restrict__ out)
{
    __shared__ float sJ[128 * KD];             // 8 KB
    __shared__ float sI[128 * KD];             // 8 KB
    __shared__ int last;

    const int o   = blockIdx.x;
    const int jc  = blockIdx.y;                // j-chunk (128 j's)
    const int q   = blockIdx.z;                // i-quarter (128 i's)
    const int tid = threadIdx.x;
    const int j   = jc * 128 + tid;

    // Stage j-rows and i-rows, summing the 4 k-split partials
    {
        const int offJ = (o * B_SZ + jc * 128) * KD / 4;   // float4 units
        const int offI = (o * B_SZ + q  * 128) * KD / 4;
        float4* dJ = (float4*)sJ;
        float4* dI = (float4*)sI;
#pragma unroll
        for (int t = 0; t < 4; t++) {
            int e = tid + t * 128;
            float4 aJ = ((const float4*)g_Mp[0])[offJ + e];
            float4 bJ = ((const float4*)g_Mp[1])[offJ + e];
            float4 cJ = ((const float4*)g_Mp[2])[offJ + e];
            float4 eJ = ((const float4*)g_Mp[3])[offJ + e];
            dJ[e] = make_float4((aJ.x + bJ.x) + (cJ.x + eJ.x),
                                (aJ.y + bJ.y) + (cJ.y + eJ.y),
                                (aJ.z + bJ.z) + (cJ.z + eJ.z),
                                (aJ.w + bJ.w) + (cJ.w + eJ.w));
            float4 aI = ((const float4*)g_Mp[0])[offI + e];
            float4 bI = ((const float4*)g_Mp[1])[offI + e];
            float4 cI = ((const float4*)g_Mp[2])[offI + e];
            float4 eI = ((const float4*)g_Mp[3])[offI + e];
            dI[e] = make_float4((aI.x + bI.x) + (cI.x + eI.x),
                                (aI.y + bI.y) + (cI.y + eI.y),
                                (aI.z + bI.z) + (cI.z + eI.z),
                                (aI.w + bI.w) + (cI.w + eI.w));
        }
    }
    __syncthreads();

    // Pre-negated packed row j
    u64 mjn[8];
#pragma unroll
    for (int p = 0; p < 8; p++)
        mjn[p] = pack2(-sJ[tid * KD + 2 * p], -sJ[tid * KD + 2 * p + 1]);

    const ulonglong2* s2 = (const ulonglong2*)sI;

    // 4 independent accumulator chains
    float S0 = 0.f, S1 = 0.f, S2 = 0.f, S3 = 0.f;
#pragma unroll 2
    for (int i = 0; i < 128; i += 4) {
        S0 += pair_term(s2, mjn, i + 0);
        S1 += pair_term(s2, mjn, i + 1);
        S2 += pair_term(s2, mjn, i + 2);
        S3 += pair_term(s2, mjn, i + 3);
    }
    float S = (S0 + S1) + (S2 + S3);

    atomicAdd(&g_S[o * B_SZ + j], S);          // coalesced REDG

    // Last block of the (o, jc) group applies the finalize
    __threadfence();
    __syncthreads();
    if (tid == 0)
        last = (atomicAdd(&g_cnt[o * 4 + jc], 1u) == 3u);
    __syncthreads();
    if (last) {
        __threadfence();                       // acquire: see peers' REDG
        float s = g_S[o * B_SZ + j];           // coalesced
        out[j * OUT_F + o] = w[j] * (s - 1.0f);
        if (tid == 0) g_cnt[o * 4 + jc] = 0u;  // reset for next graph replay
    }
}

// ---------------------------------------------------------------------------
extern "C" void kernel_launch(void* const* d_in, const int* in_sizes, int n_in,
                              void* d_out, int out_size)
{
    const float* x = (const float*)d_in[0];   // [512, 512]
    const float* w = (const float*)d_in[1];   // [1, 512]
    const float* T = (const float*)d_in[2];   // [512, 64, 16]
    float* out = (float*)d_out;               // [512, 64]

    (void)in_sizes; (void)n_in; (void)out_size;

    mbd_gemm_kernel<<<dim3(NF / TN, B_SZ / TM, KS), 256>>>(x, T);
    mbd_pairwise_kernel<<<dim3(OUT_F, 4, 4), 128>>>(w, out);
}

// round 10
// speedup vs baseline: 1.8287x; 1.1140x over previous
#include <cuda_runtime.h>
#include <cuda_bf16.h>

// Problem constants
#define B_SZ   512
#define IN_F   512
#define OUT_F  64
#define KD     16
#define NF     (OUT_F * KD)   // 1024
#define KS     4              // k-splits in GEMM

typedef unsigned long long u64;
typedef unsigned int u32;

// Scratch: 4 partial M buffers [o][b][k]; S accumulator [o][j]; group counters
__device__ float g_Mp[KS][OUT_F * B_SZ * KD];
__device__ float g_S[OUT_F * B_SZ];
__device__ unsigned int g_cnt[OUT_F * 4];      // zero-init, self-resetting

// ---- packed helpers (sm_103a) ---------------------------------------------
__device__ __forceinline__ u64 ffma2(u64 a, u64 b, u64 c) {
    u64 r; asm("fma.rn.f32x2 %0, %1, %2, %3;" : "=l"(r) : "l"(a), "l"(b), "l"(c)); return r;
}
__device__ __forceinline__ u32 hadd2b(u32 a, u32 b) {
    u32 r; asm("add.rn.bf16x2 %0, %1, %2;" : "=r"(r) : "r"(a), "r"(b)); return r;
}
__device__ __forceinline__ u32 habs2(u32 a) { return a & 0x7FFF7FFFu; }
// pack two f32 into bf16x2: lo -> low half, hi -> high half
__device__ __forceinline__ u32 cvt2(float lo, float hi) {
    u32 r; asm("cvt.rn.bf16x2.f32 %0, %1, %2;" : "=r"(r) : "f"(hi), "f"(lo)); return r;
}

// ---------------------------------------------------------------------------
// Kernel A: k-split GEMM, double-buffered (UNCHANGED from R8/R9).
// ---------------------------------------------------------------------------
#define TM 64
#define TN 64
#define TK 16
#define KC (IN_F / KS)        // 128
#define NSTEP (KC / TK)       // 8

__global__ __launch_bounds__(256) void mbd_gemm_kernel(
    const float* __restrict__ x, const float* __restrict__ T)
{
    __shared__ float2 xsd[2][TM][TK + 1];   // duplicated A (a,a)
    __shared__ float  Ts[2][TK][TN];

    const int tid = threadIdx.x;
    const int nt  = blockIdx.x;
    const int mt  = blockIdx.y;
    const int ks  = blockIdx.z;

    if (ks == 0) {
        int id = mt * 16 + nt;
        g_S[id * 256 + tid] = 0.0f;
    }

    const int tx = tid & 15;
    const int ty = tid >> 4;
    const int m0 = mt * TM;
    const int n0 = nt * TN;
    const int kb = ks * KC;
    const int r = ty * 4;
    const int c = tx * 4;

    const int lm = (tid * 4) >> 4, lk = (tid * 4) & 15;
    const int bk = (tid * 4) >> 6, bn = (tid * 4) & 63;
    const float* xp = &x[(m0 + lm) * IN_F + kb + lk];
    const float* Tp = &T[(kb + bk) * NF + n0 + bn];

    u64 acc[4][2];
#pragma unroll
    for (int i = 0; i < 4; i++) { acc[i][0] = 0ULL; acc[i][1] = 0ULL; }

    {
        float4 va = *(const float4*)xp;
        float4 vb = *(const float4*)Tp;
        xsd[0][lm][lk + 0] = make_float2(va.x, va.x);
        xsd[0][lm][lk + 1] = make_float2(va.y, va.y);
        xsd[0][lm][lk + 2] = make_float2(va.z, va.z);
        xsd[0][lm][lk + 3] = make_float2(va.w, va.w);
        *(float4*)&Ts[0][bk][bn] = vb;
    }

    int buf = 0;
#pragma unroll
    for (int s = 0; s < NSTEP; s++) {
        __syncthreads();

        float4 na, nb;
        if (s < NSTEP - 1) {
            na = *(const float4*)(xp + (s + 1) * TK);
            nb = *(const float4*)(Tp + (s + 1) * TK * NF);
        }

#pragma unroll
        for (int kk = 0; kk < TK; kk++) {
            u64 a0 = *(const u64*)&xsd[buf][r + 0][kk];
            u64 a1 = *(const u64*)&xsd[buf][r + 1][kk];
            u64 a2 = *(const u64*)&xsd[buf][r + 2][kk];
            u64 a3 = *(const u64*)&xsd[buf][r + 3][kk];
            ulonglong2 bb = *(const ulonglong2*)&Ts[buf][kk][c];
            acc[0][0] = ffma2(a0, bb.x, acc[0][0]); acc[0][1] = ffma2(a0, bb.y, acc[0][1]);
            acc[1][0] = ffma2(a1, bb.x, acc[1][0]); acc[1][1] = ffma2(a1, bb.y, acc[1][1]);
            acc[2][0] = ffma2(a2, bb.x, acc[2][0]); acc[2][1] = ffma2(a2, bb.y, acc[2][1]);
            acc[3][0] = ffma2(a3, bb.x, acc[3][0]); acc[3][1] = ffma2(a3, bb.y, acc[3][1]);
        }

        if (s < NSTEP - 1) {
            int nb2 = buf ^ 1;
            xsd[nb2][lm][lk + 0] = make_float2(na.x, na.x);
            xsd[nb2][lm][lk + 1] = make_float2(na.y, na.y);
            xsd[nb2][lm][lk + 2] = make_float2(na.z, na.z);
            xsd[nb2][lm][lk + 3] = make_float2(na.w, na.w);
            *(float4*)&Ts[nb2][bk][bn] = nb;
        }
        buf ^= 1;
    }

    const int of = n0 + c;
    const int o  = of >> 4;
    const int k  = of & 15;
    float* dst = g_Mp[ks];
#pragma unroll
    for (int ii = 0; ii < 4; ii++) {
        int b = m0 + r + ii;
        ulonglong2 v; v.x = acc[ii][0]; v.y = acc[ii][1];
        *(ulonglong2*)&dst[(o * B_SZ + b) * KD + k] = v;
    }
}

// ---------------------------------------------------------------------------
// Kernel B: pairwise tiles + fused finalize.
// CHANGE vs R9: inner loop in bf16x2 (16 k-values in 8 regs) — halves the
// abs LOP3 count and the LDS traffic. Rows bf16-converted once at staging;
// identical rounding for j and i rows keeps the diagonal term exactly 1.
// ---------------------------------------------------------------------------
__device__ __forceinline__ float bterm(const uint4* __restrict__ s4,
                                       const u32* __restrict__ mjn, int i)
{
    uint4 va = s4[i * 2 + 0];                  // ks 0..7  (bf16x2 x4)
    uint4 vb = s4[i * 2 + 1];                  // ks 8..15
    u32 d0 = habs2(hadd2b(va.x, mjn[0]));
    u32 d1 = habs2(hadd2b(va.y, mjn[1]));
    u32 d2 = habs2(hadd2b(va.z, mjn[2]));
    u32 d3 = habs2(hadd2b(va.w, mjn[3]));
    u32 d4 = habs2(hadd2b(vb.x, mjn[4]));
    u32 d5 = habs2(hadd2b(vb.y, mjn[5]));
    u32 d6 = habs2(hadd2b(vb.z, mjn[6]));
    u32 d7 = habs2(hadd2b(vb.w, mjn[7]));
    u32 t = hadd2b(hadd2b(hadd2b(d0, d1), hadd2b(d2, d3)),
                   hadd2b(hadd2b(d4, d5), hadd2b(d6, d7)));
    float lo = __uint_as_float(t << 16);          // bf16 -> f32 reinterpret
    float hi = __uint_as_float(t & 0xFFFF0000u);
    return __expf(-(lo + hi));
}

__global__ __launch_bounds__(128) void mbd_pairwise_kernel(
    const float* __restrict__ w, float* __restrict__ out)
{
    __shared__ u32 sJb[128 * 8];               // bf16x2 rows, 4 KB
    __shared__ u32 sIb[128 * 8];               // 4 KB
    __shared__ int last;

    const int o   = blockIdx.x;
    const int jc  = blockIdx.y;                // j-chunk (128 j's)
    const int q   = blockIdx.z;                // i-quarter (128 i's)
    const int tid = threadIdx.x;
    const int j   = jc * 128 + tid;

    // Stage: sum the 4 k-split partials in fp32, convert to bf16x2
    {
        const int offJ = (o * B_SZ + jc * 128) * KD / 4;   // float4 units
        const int offI = (o * B_SZ + q  * 128) * KD / 4;
#pragma unroll
        for (int t = 0; t < 4; t++) {
            int e = tid + t * 128;
            float4 aJ = ((const float4*)g_Mp[0])[offJ + e];
            float4 bJ = ((const float4*)g_Mp[1])[offJ + e];
            float4 cJ = ((const float4*)g_Mp[2])[offJ + e];
            float4 eJ = ((const float4*)g_Mp[3])[offJ + e];
            float jx = (aJ.x + bJ.x) + (cJ.x + eJ.x);
            float jy = (aJ.y + bJ.y) + (cJ.y + eJ.y);
            float jz = (aJ.z + bJ.z) + (cJ.z + eJ.z);
            float jw = (aJ.w + bJ.w) + (cJ.w + eJ.w);
            sJb[e * 2 + 0] = cvt2(jx, jy);
            sJb[e * 2 + 1] = cvt2(jz, jw);
            float4 aI = ((const float4*)g_Mp[0])[offI + e];
            float4 bI = ((const float4*)g_Mp[1])[offI + e];
            float4 cI = ((const float4*)g_Mp[2])[offI + e];
            float4 eI = ((const float4*)g_Mp[3])[offI + e];
            float ix = (aI.x + bI.x) + (cI.x + eI.x);
            float iy = (aI.y + bI.y) + (cI.y + eI.y);
            float iz = (aI.z + bI.z) + (cI.z + eI.z);
            float iw = (aI.w + bI.w) + (cI.w + eI.w);
            sIb[e * 2 + 0] = cvt2(ix, iy);
            sIb[e * 2 + 1] = cvt2(iz, iw);
        }
    }
    __syncthreads();

    // Negated bf16x2 row j (sign flip is exact)
    u32 mjn[8];
#pragma unroll
    for (int p = 0; p < 8; p++)
        mjn[p] = sJb[tid * 8 + p] ^ 0x80008000u;

    const uint4* s4 = (const uint4*)sIb;

    float S0 = 0.f, S1 = 0.f, S2 = 0.f, S3 = 0.f;
#pragma unroll 2
    for (int i = 0; i < 128; i += 4) {
        S0 += bterm(s4, mjn, i + 0);
        S1 += bterm(s4, mjn, i + 1);
        S2 += bterm(s4, mjn, i + 2);
        S3 += bterm(s4, mjn, i + 3);
    }
    float S = (S0 + S1) + (S2 + S3);

    atomicAdd(&g_S[o * B_SZ + j], S);          // coalesced REDG

    // Last block of the (o, jc) group applies the finalize
    __threadfence();
    __syncthreads();
    if (tid == 0)
        last = (atomicAdd(&g_cnt[o * 4 + jc], 1u) == 3u);
    __syncthreads();
    if (last) {
        __threadfence();                       // acquire: see peers' REDG
        float s = g_S[o * B_SZ + j];           // coalesced
        out[j * OUT_F + o] = w[j] * (s - 1.0f);
        if (tid == 0) g_cnt[o * 4 + jc] = 0u;  // reset for next graph replay
    }
}

// ---------------------------------------------------------------------------
extern "C" void kernel_launch(void* const* d_in, const int* in_sizes, int n_in,
                              void* d_out, int out_size)
{
    const float* x = (const float*)d_in[0];   // [512, 512]
    const float* w = (const float*)d_in[1];   // [1, 512]
    const float* T = (const float*)d_in[2];   // [512, 64, 16]
    float* out = (float*)d_out;               // [512, 64]

    (void)in_sizes; (void)n_in; (void)out_size;

    mbd_gemm_kernel<<<dim3(NF / TN, B_SZ / TM, KS), 256>>>(x, T);
    mbd_pairwise_kernel<<<dim3(OUT_F, 4, 4), 128>>>(w, out);
}

// round 11
// speedup vs baseline: 1.8378x; 1.0050x over previous
#include <cuda_runtime.h>
#include <cuda_bf16.h>

// Problem constants
#define B_SZ   512
#define IN_F   512
#define OUT_F  64
#define KD     16
#define NF     (OUT_F * KD)   // 1024
#define KS     4              // k-splits in GEMM

typedef unsigned long long u64;
typedef unsigned int u32;

// Scratch: 4 bf16 partial M buffers [o][b][k-pairs]; S accum [o][j]; counters
__device__ u32 g_Mpb[KS][OUT_F * B_SZ * KD / 2];   // bf16x2, 1 MB per split
__device__ float g_S[OUT_F * B_SZ];
__device__ unsigned int g_cnt[OUT_F * 4];          // zero-init, self-resetting

// ---- packed helpers (sm_103a) ---------------------------------------------
__device__ __forceinline__ u64 ffma2(u64 a, u64 b, u64 c) {
    u64 r; asm("fma.rn.f32x2 %0, %1, %2, %3;" : "=l"(r) : "l"(a), "l"(b), "l"(c)); return r;
}
__device__ __forceinline__ u32 hadd2b(u32 a, u32 b) {
    u32 r; asm("add.rn.bf16x2 %0, %1, %2;" : "=r"(r) : "r"(a), "r"(b)); return r;
}
__device__ __forceinline__ u32 habs2(u32 a) { return a & 0x7FFF7FFFu; }
// pack two f32 into bf16x2: lo -> low half, hi -> high half
__device__ __forceinline__ u32 cvt2(float lo, float hi) {
    u32 r; asm("cvt.rn.bf16x2.f32 %0, %1, %2;" : "=r"(r) : "f"(hi), "f"(lo)); return r;
}
__device__ __forceinline__ void unpack2(u64 v, float& lo, float& hi) {
    asm("mov.b64 {%0, %1}, %2;" : "=f"(lo), "=f"(hi) : "l"(v));
}
// 4-way bf16x2 sum with FIXED op order (identical for J and I staging)
__device__ __forceinline__ uint4 sum4(uint4 a, uint4 b, uint4 c, uint4 d) {
    uint4 r;
    r.x = hadd2b(hadd2b(a.x, b.x), hadd2b(c.x, d.x));
    r.y = hadd2b(hadd2b(a.y, b.y), hadd2b(c.y, d.y));
    r.z = hadd2b(hadd2b(a.z, b.z), hadd2b(c.z, d.z));
    r.w = hadd2b(hadd2b(a.w, b.w), hadd2b(c.w, d.w));
    return r;
}

// ---------------------------------------------------------------------------
// Kernel A: k-split GEMM, double-buffered, TK=32 (4 steps), bf16 epilogue.
// Block (nt, mt, ks): 64x64 tile over K-chunk 128 -> g_Mpb[ks][o][b][k].
// ---------------------------------------------------------------------------
#define TM 64
#define TN 64
#define TK 32
#define KC (IN_F / KS)        // 128
#define NSTEP (KC / TK)       // 4

__global__ __launch_bounds__(256) void mbd_gemm_kernel(
    const float* __restrict__ x, const float* __restrict__ T)
{
    __shared__ float2 xsd[2][TM][TK + 1];   // duplicated A (a,a), 33.8 KB
    __shared__ float  Ts[2][TK][TN];        // 16 KB

    const int tid = threadIdx.x;
    const int nt  = blockIdx.x;
    const int mt  = blockIdx.y;
    const int ks  = blockIdx.z;

    if (ks == 0) {
        int id = mt * 16 + nt;
        g_S[id * 256 + tid] = 0.0f;
    }

    const int tx = tid & 15;
    const int ty = tid >> 4;
    const int m0 = mt * TM;
    const int n0 = nt * TN;
    const int kb = ks * KC;
    const int r = ty * 4;
    const int c = tx * 4;

    // Loader coords: A tile 64x32 (2 float4/thread, rows lm and lm+32),
    //                B tile 32x64 (2 float4/thread, rows bk and bk+16)
    const int lm = (tid * 4) >> 5, lk = (tid * 4) & 31;
    const int bk = (tid * 4) >> 6, bn = (tid * 4) & 63;
    const float* xp0 = &x[(m0 + lm) * IN_F + kb + lk];
    const float* xp1 = xp0 + 32 * IN_F;
    const float* Tp0 = &T[(kb + bk) * NF + n0 + bn];
    const float* Tp1 = Tp0 + 16 * NF;

    u64 acc[4][2];
#pragma unroll
    for (int i = 0; i < 4; i++) { acc[i][0] = 0ULL; acc[i][1] = 0ULL; }

    // Prologue: stage step 0 into buffer 0
    {
        float4 a0 = *(const float4*)xp0;
        float4 a1 = *(const float4*)xp1;
        float4 b0 = *(const float4*)Tp0;
        float4 b1 = *(const float4*)Tp1;
        xsd[0][lm][lk + 0] = make_float2(a0.x, a0.x);
        xsd[0][lm][lk + 1] = make_float2(a0.y, a0.y);
        xsd[0][lm][lk + 2] = make_float2(a0.z, a0.z);
        xsd[0][lm][lk + 3] = make_float2(a0.w, a0.w);
        xsd[0][lm + 32][lk + 0] = make_float2(a1.x, a1.x);
        xsd[0][lm + 32][lk + 1] = make_float2(a1.y, a1.y);
        xsd[0][lm + 32][lk + 2] = make_float2(a1.z, a1.z);
        xsd[0][lm + 32][lk + 3] = make_float2(a1.w, a1.w);
        *(float4*)&Ts[0][bk][bn] = b0;
        *(float4*)&Ts[0][bk + 16][bn] = b1;
    }

    int buf = 0;
#pragma unroll
    for (int s = 0; s < NSTEP; s++) {
        __syncthreads();

        float4 na0, na1, nb0, nb1;
        if (s < NSTEP - 1) {
            na0 = *(const float4*)(xp0 + (s + 1) * TK);
            na1 = *(const float4*)(xp1 + (s + 1) * TK);
            nb0 = *(const float4*)(Tp0 + (s + 1) * TK * NF);
            nb1 = *(const float4*)(Tp1 + (s + 1) * TK * NF);
        }

#pragma unroll
        for (int kk = 0; kk < TK; kk++) {
            u64 a0 = *(const u64*)&xsd[buf][r + 0][kk];
            u64 a1 = *(const u64*)&xsd[buf][r + 1][kk];
            u64 a2 = *(const u64*)&xsd[buf][r + 2][kk];
            u64 a3 = *(const u64*)&xsd[buf][r + 3][kk];
            ulonglong2 bb = *(const ulonglong2*)&Ts[buf][kk][c];
            acc[0][0] = ffma2(a0, bb.x, acc[0][0]); acc[0][1] = ffma2(a0, bb.y, acc[0][1]);
            acc[1][0] = ffma2(a1, bb.x, acc[1][0]); acc[1][1] = ffma2(a1, bb.y, acc[1][1]);
            acc[2][0] = ffma2(a2, bb.x, acc[2][0]); acc[2][1] = ffma2(a2, bb.y, acc[2][1]);
            acc[3][0] = ffma2(a3, bb.x, acc[3][0]); acc[3][1] = ffma2(a3, bb.y, acc[3][1]);
        }

        if (s < NSTEP - 1) {
            int b2 = buf ^ 1;
            xsd[b2][lm][lk + 0] = make_float2(na0.x, na0.x);
            xsd[b2][lm][lk + 1] = make_float2(na0.y, na0.y);
            xsd[b2][lm][lk + 2] = make_float2(na0.z, na0.z);
            xsd[b2][lm][lk + 3] = make_float2(na0.w, na0.w);
            xsd[b2][lm + 32][lk + 0] = make_float2(na1.x, na1.x);
            xsd[b2][lm + 32][lk + 1] = make_float2(na1.y, na1.y);
            xsd[b2][lm + 32][lk + 2] = make_float2(na1.z, na1.z);
            xsd[b2][lm + 32][lk + 3] = make_float2(na1.w, na1.w);
            *(float4*)&Ts[b2][bk][bn] = nb0;
            *(float4*)&Ts[b2][bk + 16][bn] = nb1;
        }
        buf ^= 1;
    }

    // Epilogue: convert 4 fp32 cols -> 2 bf16x2, store uint2.
    // of = n0 + c : 4 consecutive cols inside one o; k multiple of 4.
    const int of = n0 + c;
    const int o  = of >> 4;
    const int k  = of & 15;
    u32* dst = g_Mpb[ks];
#pragma unroll
    for (int ii = 0; ii < 4; ii++) {
        int b = m0 + r + ii;
        float c0, c1, c2, c3;
        unpack2(acc[ii][0], c0, c1);
        unpack2(acc[ii][1], c2, c3);
        uint2 v; v.x = cvt2(c0, c1); v.y = cvt2(c2, c3);
        *(uint2*)&dst[(o * B_SZ + b) * (KD / 2) + k / 2] = v;
    }
}

// ---------------------------------------------------------------------------
// Kernel B: pairwise tiles + fused finalize.
// CHANGE vs R10: staging reads bf16 partials (half traffic), sums in bf16x2
// with identical op order for J and I (keeps diagonal exactly zero).
// ---------------------------------------------------------------------------
__device__ __forceinline__ float bterm(const uint4* __restrict__ s4,
                                       const u32* __restrict__ mjn, int i)
{
    uint4 va = s4[i * 2 + 0];                  // ks 0..7  (bf16x2 x4)
    uint4 vb = s4[i * 2 + 1];                  // ks 8..15
    u32 d0 = habs2(hadd2b(va.x, mjn[0]));
    u32 d1 = habs2(hadd2b(va.y, mjn[1]));
    u32 d2 = habs2(hadd2b(va.z, mjn[2]));
    u32 d3 = habs2(hadd2b(va.w, mjn[3]));
    u32 d4 = habs2(hadd2b(vb.x, mjn[4]));
    u32 d5 = habs2(hadd2b(vb.y, mjn[5]));
    u32 d6 = habs2(hadd2b(vb.z, mjn[6]));
    u32 d7 = habs2(hadd2b(vb.w, mjn[7]));
    u32 t = hadd2b(hadd2b(hadd2b(d0, d1), hadd2b(d2, d3)),
                   hadd2b(hadd2b(d4, d5), hadd2b(d6, d7)));
    float lo = __uint_as_float(t << 16);          // bf16 -> f32 reinterpret
    float hi = __uint_as_float(t & 0xFFFF0000u);
    return __expf(-(lo + hi));
}

__global__ __launch_bounds__(128) void mbd_pairwise_kernel(
    const float* __restrict__ w, float* __restrict__ out)
{
    __shared__ u32 sJb[128 * 8];               // bf16x2 rows, 4 KB
    __shared__ u32 sIb[128 * 8];               // 4 KB
    __shared__ int last;

    const int o   = blockIdx.x;
    const int jc  = blockIdx.y;                // j-chunk (128 j's)
    const int q   = blockIdx.z;                // i-quarter (128 i's)
    const int tid = threadIdx.x;
    const int j   = jc * 128 + tid;

    // Stage: sum the 4 bf16 partials (uint4 = 8 bf16 values each)
    {
        const int offJ4 = (o * B_SZ + jc * 128) * 2;   // uint4 units (2/row)
        const int offI4 = (o * B_SZ + q  * 128) * 2;
#pragma unroll
        for (int t = 0; t < 2; t++) {
            int e = tid + t * 128;                     // 0..255
            uint4 aJ = ((const uint4*)g_Mpb[0])[offJ4 + e];
            uint4 bJ = ((const uint4*)g_Mpb[1])[offJ4 + e];
            uint4 cJ = ((const uint4*)g_Mpb[2])[offJ4 + e];
            uint4 dJ = ((const uint4*)g_Mpb[3])[offJ4 + e];
            ((uint4*)sJb)[e] = sum4(aJ, bJ, cJ, dJ);
            uint4 aI = ((const uint4*)g_Mpb[0])[offI4 + e];
            uint4 bI = ((const uint4*)g_Mpb[1])[offI4 + e];
            uint4 cI = ((const uint4*)g_Mpb[2])[offI4 + e];
            uint4 dI = ((const uint4*)g_Mpb[3])[offI4 + e];
            ((uint4*)sIb)[e] = sum4(aI, bI, cI, dI);
        }
    }
    __syncthreads();

    // Negated bf16x2 row j (sign flip is exact)
    u32 mjn[8];
#pragma unroll
    for (int p = 0; p < 8; p++)
        mjn[p] = sJb[tid * 8 + p] ^ 0x80008000u;

    const uint4* s4 = (const uint4*)sIb;

    float S0 = 0.f, S1 = 0.f, S2 = 0.f, S3 = 0.f;
#pragma unroll 2
    for (int i = 0; i < 128; i += 4) {
        S0 += bterm(s4, mjn, i + 0);
        S1 += bterm(s4, mjn, i + 1);
        S2 += bterm(s4, mjn, i + 2);
        S3 += bterm(s4, mjn, i + 3);
    }
    float S = (S0 + S1) + (S2 + S3);

    atomicAdd(&g_S[o * B_SZ + j], S);          // coalesced REDG

    // Last block of the (o, jc) group applies the finalize
    __threadfence();
    __syncthreads();
    if (tid == 0)
        last = (atomicAdd(&g_cnt[o * 4 + jc], 1u) == 3u);
    __syncthreads();
    if (last) {
        __threadfence();                       // acquire: see peers' REDG
        float s = g_S[o * B_SZ + j];           // coalesced
        out[j * OUT_F + o] = w[j] * (s - 1.0f);
        if (tid == 0) g_cnt[o * 4 + jc] = 0u;  // reset for next graph replay
    }
}

// ---------------------------------------------------------------------------
extern "C" void kernel_launch(void* const* d_in, const int* in_sizes, int n_in,
                              void* d_out, int out_size)
{
    const float* x = (const float*)d_in[0];   // [512, 512]
    const float* w = (const float*)d_in[1];   // [1, 512]
    const float* T = (const float*)d_in[2];   // [512, 64, 16]
    float* out = (float*)d_out;               // [512, 64]

    (void)in_sizes; (void)n_in; (void)out_size;

    mbd_gemm_kernel<<<dim3(NF / TN, B_SZ / TM, KS), 256>>>(x, T);
    mbd_pairwise_kernel<<<dim3(OUT_F, 4, 4), 128>>>(w, out);
}